// round 3
// baseline (speedup 1.0000x reference)
#include <cuda_runtime.h>
#include <cstdint>
#include <cstddef>

#define BB   8
#define NPTS 4096
#define SS   2048
#define KNB  64
#define CIN  64
#define C0   67
#define HID  128
#define BSZ  (BB*SS)
#define FSTR 68
#define R2F  0.04f
#define MAXC 1024

// ---------------- device scratch (no allocs allowed) ----------------
__device__ float  g_ctr[BSZ*3];
__device__ int    g_nbr[BSZ*KNB];
__device__ int    g_cnt[BSZ];
__device__ float4 g_pos4[BB*NPTS];
__device__ float  g_H0[(size_t)BSZ*KNB*HID];   // 537 MB
__device__ float  g_H1[(size_t)BSZ*KNB*HID];   // 537 MB
__device__ double g_stat[2][2][32][HID];       // [layer][sum/sumsq][split][ch]
__device__ float  g_scale[2][HID];
__device__ float  g_shift[2][HID];

// ---------------- zero the stat accumulators every launch ----------------
__global__ void k_zero() {
    int i = blockIdx.x * blockDim.x + threadIdx.x;
    const int n = 2*2*32*HID;
    double* p = &g_stat[0][0][0][0];
    for (; i < n; i += gridDim.x * blockDim.x) p[i] = 0.0;
}

// ---------------- pad pos -> float4 ----------------
__global__ void k_pos4(const float* __restrict__ pos) {
    int i = blockIdx.x * blockDim.x + threadIdx.x;
    if (i < BB*NPTS)
        g_pos4[i] = make_float4(pos[3*i], pos[3*i+1], pos[3*i+2], 0.f);
}

// ---------------- farthest point sampling: 1 block / cloud ----------------
__global__ void __launch_bounds__(1024) k_fps(const float* __restrict__ pos,
                                              float* __restrict__ octr,
                                              float* __restrict__ obat) {
    int b = blockIdx.x, t = threadIdx.x;
    const float* p = pos + (size_t)b * NPTS * 3;
    float px[4], py[4], pz[4], md[4];
#pragma unroll
    for (int j = 0; j < 4; j++) {
        int i = t + j * 1024;
        px[j] = p[3*i]; py[j] = p[3*i+1]; pz[j] = p[3*i+2];
        md[j] = __int_as_float(0x7f800000);  // +inf
    }
    __shared__ float sv[32];
    __shared__ int   si[32];
    __shared__ int   sLast;
    int lane = t & 31, w = t >> 5;
    int last = 0;
    for (int s = 0; s < SS; s++) {
        float qx = p[3*last], qy = p[3*last+1], qz = p[3*last+2];
        if (t == 0) {
            int o = b*SS + s;
            g_ctr[o*3] = qx; g_ctr[o*3+1] = qy; g_ctr[o*3+2] = qz;
            if (octr) { octr[o*3] = qx; octr[o*3+1] = qy; octr[o*3+2] = qz; }
            if (obat) obat[o] = (float)b;
        }
        float bv = -1.f; int bi = 0;
#pragma unroll
        for (int j = 0; j < 4; j++) {
            float dx = px[j]-qx, dy = py[j]-qy, dz = pz[j]-qz;
            float d = fmaf(dz, dz, fmaf(dy, dy, __fmul_rn(dx, dx)));
            md[j] = fminf(md[j], d);
            if (md[j] > bv) { bv = md[j]; bi = t + j*1024; }  // strict > : lowest idx wins
        }
#pragma unroll
        for (int off = 16; off > 0; off >>= 1) {
            float ov = __shfl_down_sync(0xffffffffu, bv, off);
            int   oi = __shfl_down_sync(0xffffffffu, bi, off);
            if (ov > bv || (ov == bv && oi < bi)) { bv = ov; bi = oi; }
        }
        if (lane == 0) { sv[w] = bv; si[w] = bi; }
        __syncthreads();
        if (w == 0) {
            bv = sv[lane]; bi = si[lane];
#pragma unroll
            for (int off = 16; off > 0; off >>= 1) {
                float ov = __shfl_down_sync(0xffffffffu, bv, off);
                int   oi = __shfl_down_sync(0xffffffffu, bi, off);
                if (ov > bv || (ov == bv && oi < bi)) { bv = ov; bi = oi; }
            }
            if (lane == 0) sLast = bi;
        }
        __syncthreads();
        last = sLast;
    }
}

// ---------------- radius-capped kNN (set only): 1 block / centroid ----------------
__global__ void __launch_bounds__(128) k_nbr() {
    int c = blockIdx.x, t = threadIdx.x;
    int b = c >> 11;  // /SS
    __shared__ float sd[MAXC];
    __shared__ int   sid[MAXC];
    __shared__ int   hist[128];
    __shared__ int   sc, so, s_tb, s_m, tc;
    __shared__ float td[256];
    __shared__ int   tdi[256];
    __shared__ int   wtot[4];
    if (t == 0) { sc = 0; so = 0; tc = 0; }
    hist[t] = 0;
    float cx = g_ctr[c*3], cy = g_ctr[c*3+1], cz = g_ctr[c*3+2];
    __syncthreads();
    for (int i = t; i < NPTS; i += 128) {
        float4 P = g_pos4[b*NPTS + i];
        float dx = P.x-cx, dy = P.y-cy, dz = P.z-cz;
        float d = fmaf(dz, dz, fmaf(dy, dy, __fmul_rn(dx, dx)));
        if (d <= R2F) {
            int k = atomicAdd(&sc, 1);
            if (k < MAXC) { sd[k] = d; sid[k] = i; }
        }
    }
    __syncthreads();
    int cnt = min(sc, MAXC);
    if (cnt <= KNB) {                    // everything in radius survives: order irrelevant
        if (t < cnt) g_nbr[c*KNB + t] = sid[t];
        if (t == 0) g_cnt[c] = cnt;
        return;
    }
    // bucket histogram over d2
    const float bsc = 128.0f / R2F;
    for (int i = t; i < cnt; i += 128) {
        int bk = min(127, (int)(sd[i] * bsc));
        atomicAdd(&hist[bk], 1);
    }
    __syncthreads();
    {   // 128-wide inclusive scan, find pivot bucket
        int lane = t & 31, w = t >> 5;
        int h = hist[t], v = h;
#pragma unroll
        for (int o = 1; o < 32; o <<= 1) {
            int u = __shfl_up_sync(0xffffffffu, v, o);
            if (lane >= o) v += u;
        }
        if (lane == 31) wtot[w] = v;
        __syncthreads();
        int base = 0;
        for (int k2 = 0; k2 < w; k2++) base += wtot[k2];
        int incl = v + base, excl = incl - h;
        if (incl >= KNB && excl < KNB) { s_tb = t; s_m = excl; }
    }
    __syncthreads();
    int tb = s_tb, m = s_m;
    for (int i = t; i < cnt; i += 128) {
        int bk = min(127, (int)(sd[i] * bsc));
        if (bk < tb) {
            int k = atomicAdd(&so, 1);
            g_nbr[c*KNB + k] = sid[i];
        } else if (bk == tb) {
            int k = atomicAdd(&tc, 1);
            if (k < 256) { td[k] = sd[i]; tdi[k] = sid[i]; }
        }
    }
    __syncthreads();
    int bn = min(tc, 256), rem = KNB - m;
    for (int i = t; i < bn; i += 128) {   // rank-select inside the boundary bucket
        float di = td[i]; int ii = tdi[i];
        int rank = 0;
        for (int j2 = 0; j2 < bn; j2++) {
            float dj = td[j2]; int ij = tdi[j2];
            if (dj < di || (dj == di && ij < ii)) rank++;
        }
        if (rank < rem) {
            int k = atomicAdd(&so, 1);
            g_nbr[c*KNB + k] = tdi[i];
        }
    }
    if (t == 0) g_cnt[c] = KNB;
}

// ---------------- layer 0: feat[64x67] @ W0[67x128] + b0, stats ----------------
__global__ void __launch_bounds__(128) k_l0(const float* __restrict__ x,
                                            const float* __restrict__ W0,
                                            const float* __restrict__ b0) {
    extern __shared__ float sm[];
    float* sW   = sm;                 // C0*HID
    float* sF   = sW + C0*HID;        // C0*FSTR
    float* sB   = sF + C0*FSTR;       // HID
    float* sSum = sB + HID;           // HID
    float* sSsq = sSum + HID;         // HID
    int c = blockIdx.x, t = threadIdx.x;
    int b = c >> 11;
    int cnt = g_cnt[c];
    for (int i = t; i < C0*HID; i += 128) sW[i] = W0[i];
    sB[t] = b0[t]; sSum[t] = 0.f; sSsq[t] = 0.f;

    int e = t >> 1, h = t & 1;
    float cx = g_ctr[c*3], cy = g_ctr[c*3+1], cz = g_ctr[c*3+2];
    if (e < cnt) {
        int j = g_nbr[c*KNB + e];
        const float4* xr = (const float4*)(x + (size_t)(b*NPTS + j)*CIN) + h*8;
#pragma unroll
        for (int k = 0; k < 8; k++) {
            float4 v = xr[k]; int cb = h*32 + k*4;
            sF[(cb+0)*FSTR + e] = v.x; sF[(cb+1)*FSTR + e] = v.y;
            sF[(cb+2)*FSTR + e] = v.z; sF[(cb+3)*FSTR + e] = v.w;
        }
        if (h == 0) {
            float4 P = g_pos4[b*NPTS + j];
            sF[64*FSTR + e] = P.x - cx;
            sF[65*FSTR + e] = P.y - cy;
            sF[66*FSTR + e] = P.z - cz;
        }
    } else {
#pragma unroll
        for (int k = 0; k < 8; k++) {
            int cb = h*32 + k*4;
            sF[(cb+0)*FSTR + e] = 0.f; sF[(cb+1)*FSTR + e] = 0.f;
            sF[(cb+2)*FSTR + e] = 0.f; sF[(cb+3)*FSTR + e] = 0.f;
        }
        if (h == 0) { sF[64*FSTR+e] = 0.f; sF[65*FSTR+e] = 0.f; sF[66*FSTR+e] = 0.f; }
    }
    __syncthreads();

    int eg = (t >> 4) * 8, cg = (t & 15) * 8;
    float acc[8][8];
#pragma unroll
    for (int i = 0; i < 8; i++)
#pragma unroll
        for (int j = 0; j < 8; j++) acc[i][j] = 0.f;

    for (int cc = 0; cc < C0; cc++) {
        float4 f0 = *(float4*)&sF[cc*FSTR + eg];
        float4 f1 = *(float4*)&sF[cc*FSTR + eg + 4];
        float4 w0 = *(float4*)&sW[cc*HID + cg];
        float4 w1 = *(float4*)&sW[cc*HID + cg + 4];
        float f[8] = {f0.x,f0.y,f0.z,f0.w,f1.x,f1.y,f1.z,f1.w};
        float wv[8] = {w0.x,w0.y,w0.z,w0.w,w1.x,w1.y,w1.z,w1.w};
#pragma unroll
        for (int i = 0; i < 8; i++)
#pragma unroll
            for (int j = 0; j < 8; j++)
                acc[i][j] = fmaf(f[i], wv[j], acc[i][j]);
    }

    float psum[8] = {0,0,0,0,0,0,0,0}, psq[8] = {0,0,0,0,0,0,0,0};
#pragma unroll
    for (int i = 0; i < 8; i++) {
        int e2 = eg + i;
        bool val = e2 < cnt;
        float z[8];
#pragma unroll
        for (int j = 0; j < 8; j++) z[j] = acc[i][j] + sB[cg+j];
        float* gp = g_H0 + ((size_t)c*KNB + e2)*HID + cg;
        *(float4*)gp     = make_float4(z[0],z[1],z[2],z[3]);
        *(float4*)(gp+4) = make_float4(z[4],z[5],z[6],z[7]);
        if (val) {
#pragma unroll
            for (int j = 0; j < 8; j++) { psum[j] += z[j]; psq[j] = fmaf(z[j], z[j], psq[j]); }
        }
    }
#pragma unroll
    for (int j = 0; j < 8; j++) {
        atomicAdd(&sSum[cg+j], psum[j]);
        atomicAdd(&sSsq[cg+j], psq[j]);
    }
    __syncthreads();
    atomicAdd(&g_stat[0][0][c & 31][t], (double)sSum[t]);
    atomicAdd(&g_stat[0][1][c & 31][t], (double)sSsq[t]);
}

// ---------------- bn prepare: scale/shift from global stats ----------------
__global__ void k_prep(const float* __restrict__ gamma,
                       const float* __restrict__ beta, int layer) {
    int t = threadIdx.x;  // 128
    int local = 0;
    for (int i = t; i < BSZ; i += 128) local += g_cnt[i];
    __shared__ int sred[4];
    int lane = t & 31, w = t >> 5;
#pragma unroll
    for (int off = 16; off > 0; off >>= 1)
        local += __shfl_down_sync(0xffffffffu, local, off);
    if (lane == 0) sred[w] = local;
    __syncthreads();
    double cntd = (double)(sred[0] + sred[1] + sred[2] + sred[3]);
    double s = 0.0, q = 0.0;
    for (int k = 0; k < 32; k++) {
        s += g_stat[layer][0][k][t];
        q += g_stat[layer][1][k][t];
    }
    double mean = s / cntd;
    double var = q / cntd - mean * mean;
    if (var < 0.0) var = 0.0;
    double a = (double)gamma[t] * rsqrt(var + 1e-5);
    g_scale[layer][t] = (float)a;
    g_shift[layer][t] = (float)((double)beta[t] - mean * a);
}

// ---------------- layer 1: bnrelu0(H0) @ W1 + b1, stats ----------------
__global__ void __launch_bounds__(128) k_l1(const float* __restrict__ W1,
                                            const float* __restrict__ b1) {
    extern __shared__ float sm[];
    float* sW   = sm;                  // HID*HID
    float* sF   = sW + HID*HID;        // HID*FSTR
    float* sB   = sF + HID*FSTR;
    float* sSc  = sB + HID;
    float* sSh  = sSc + HID;
    float* sSum = sSh + HID;
    float* sSsq = sSum + HID;
    int c = blockIdx.x, t = threadIdx.x;
    int cnt = g_cnt[c];
    for (int i = t; i < HID*HID; i += 128) sW[i] = W1[i];
    sB[t] = b1[t]; sSc[t] = g_scale[0][t]; sSh[t] = g_shift[0][t];
    sSum[t] = 0.f; sSsq[t] = 0.f;
    __syncthreads();

    int e = t >> 1, h = t & 1;
    const float4* hr = (const float4*)(g_H0 + ((size_t)c*KNB + e)*HID) + h*16;
#pragma unroll
    for (int k = 0; k < 16; k++) {
        float4 v = hr[k]; int cb = h*64 + k*4;
        sF[(cb+0)*FSTR + e] = fmaxf(0.f, fmaf(v.x, sSc[cb+0], sSh[cb+0]));
        sF[(cb+1)*FSTR + e] = fmaxf(0.f, fmaf(v.y, sSc[cb+1], sSh[cb+1]));
        sF[(cb+2)*FSTR + e] = fmaxf(0.f, fmaf(v.z, sSc[cb+2], sSh[cb+2]));
        sF[(cb+3)*FSTR + e] = fmaxf(0.f, fmaf(v.w, sSc[cb+3], sSh[cb+3]));
    }
    __syncthreads();

    int eg = (t >> 4) * 8, cg = (t & 15) * 8;
    float acc[8][8];
#pragma unroll
    for (int i = 0; i < 8; i++)
#pragma unroll
        for (int j = 0; j < 8; j++) acc[i][j] = 0.f;

    for (int cc = 0; cc < HID; cc++) {
        float4 f0 = *(float4*)&sF[cc*FSTR + eg];
        float4 f1 = *(float4*)&sF[cc*FSTR + eg + 4];
        float4 w0 = *(float4*)&sW[cc*HID + cg];
        float4 w1 = *(float4*)&sW[cc*HID + cg + 4];
        float f[8] = {f0.x,f0.y,f0.z,f0.w,f1.x,f1.y,f1.z,f1.w};
        float wv[8] = {w0.x,w0.y,w0.z,w0.w,w1.x,w1.y,w1.z,w1.w};
#pragma unroll
        for (int i = 0; i < 8; i++)
#pragma unroll
            for (int j = 0; j < 8; j++)
                acc[i][j] = fmaf(f[i], wv[j], acc[i][j]);
    }

    float psum[8] = {0,0,0,0,0,0,0,0}, psq[8] = {0,0,0,0,0,0,0,0};
#pragma unroll
    for (int i = 0; i < 8; i++) {
        int e2 = eg + i;
        bool val = e2 < cnt;
        float z[8];
#pragma unroll
        for (int j = 0; j < 8; j++) z[j] = acc[i][j] + sB[cg+j];
        float* gp = g_H1 + ((size_t)c*KNB + e2)*HID + cg;
        *(float4*)gp     = make_float4(z[0],z[1],z[2],z[3]);
        *(float4*)(gp+4) = make_float4(z[4],z[5],z[6],z[7]);
        if (val) {
#pragma unroll
            for (int j = 0; j < 8; j++) { psum[j] += z[j]; psq[j] = fmaf(z[j], z[j], psq[j]); }
        }
    }
#pragma unroll
    for (int j = 0; j < 8; j++) {
        atomicAdd(&sSum[cg+j], psum[j]);
        atomicAdd(&sSsq[cg+j], psq[j]);
    }
    __syncthreads();
    atomicAdd(&g_stat[1][0][c & 31][t], (double)sSum[t]);
    atomicAdd(&g_stat[1][1][c & 31][t], (double)sSsq[t]);
}

// ---------------- layer 2: bnrelu1(H1) @ W2 + b2, masked max ----------------
__global__ void __launch_bounds__(128) k_l2(const float* __restrict__ W2,
                                            const float* __restrict__ b2,
                                            float* __restrict__ outp) {
    extern __shared__ float sm[];
    float* sW  = sm;                   // HID*HID
    float* sF  = sW + HID*HID;         // HID*FSTR
    float* sB  = sF + HID*FSTR;
    float* sSc = sB + HID;
    float* sSh = sSc + HID;
    float* sM  = sSh + HID;            // 8*HID
    int c = blockIdx.x, t = threadIdx.x;
    int cnt = g_cnt[c];
    for (int i = t; i < HID*HID; i += 128) sW[i] = W2[i];
    sB[t] = b2[t]; sSc[t] = g_scale[1][t]; sSh[t] = g_shift[1][t];
    __syncthreads();

    int e = t >> 1, h = t & 1;
    const float4* hr = (const float4*)(g_H1 + ((size_t)c*KNB + e)*HID) + h*16;
#pragma unroll
    for (int k = 0; k < 16; k++) {
        float4 v = hr[k]; int cb = h*64 + k*4;
        sF[(cb+0)*FSTR + e] = fmaxf(0.f, fmaf(v.x, sSc[cb+0], sSh[cb+0]));
        sF[(cb+1)*FSTR + e] = fmaxf(0.f, fmaf(v.y, sSc[cb+1], sSh[cb+1]));
        sF[(cb+2)*FSTR + e] = fmaxf(0.f, fmaf(v.z, sSc[cb+2], sSh[cb+2]));
        sF[(cb+3)*FSTR + e] = fmaxf(0.f, fmaf(v.w, sSc[cb+3], sSh[cb+3]));
    }
    __syncthreads();

    int eg = (t >> 4) * 8, cg = (t & 15) * 8;
    float acc[8][8];
#pragma unroll
    for (int i = 0; i < 8; i++)
#pragma unroll
        for (int j = 0; j < 8; j++) acc[i][j] = 0.f;

    for (int cc = 0; cc < HID; cc++) {
        float4 f0 = *(float4*)&sF[cc*FSTR + eg];
        float4 f1 = *(float4*)&sF[cc*FSTR + eg + 4];
        float4 w0 = *(float4*)&sW[cc*HID + cg];
        float4 w1 = *(float4*)&sW[cc*HID + cg + 4];
        float f[8] = {f0.x,f0.y,f0.z,f0.w,f1.x,f1.y,f1.z,f1.w};
        float wv[8] = {w0.x,w0.y,w0.z,w0.w,w1.x,w1.y,w1.z,w1.w};
#pragma unroll
        for (int i = 0; i < 8; i++)
#pragma unroll
            for (int j = 0; j < 8; j++)
                acc[i][j] = fmaf(f[i], wv[j], acc[i][j]);
    }

    float mx[8];
#pragma unroll
    for (int j = 0; j < 8; j++) mx[j] = __int_as_float(0xff800000);  // -inf
#pragma unroll
    for (int i = 0; i < 8; i++) {
        int e2 = eg + i;
        if (e2 < cnt) {
#pragma unroll
            for (int j = 0; j < 8; j++)
                mx[j] = fmaxf(mx[j], acc[i][j] + sB[cg+j]);
        }
    }
    int row = t >> 4;
#pragma unroll
    for (int j = 0; j < 8; j++) sM[row*HID + cg + j] = mx[j];
    __syncthreads();
    float v = sM[t];
#pragma unroll
    for (int r = 1; r < 8; r++) v = fmaxf(v, sM[r*HID + t]);
    outp[(size_t)c*HID + t] = v;
}

// ---------------- launch ----------------
extern "C" void kernel_launch(void* const* d_in, const int* in_sizes, int n_in,
                              void* d_out, int out_size) {
    const float* x   = (const float*)d_in[0];
    const float* pos = (const float*)d_in[1];
    const float* W0  = (const float*)d_in[3];
    const float* b0  = (const float*)d_in[4];
    const float* g0  = (const float*)d_in[5];
    const float* be0 = (const float*)d_in[6];
    const float* W1  = (const float*)d_in[7];
    const float* b1  = (const float*)d_in[8];
    const float* g1  = (const float*)d_in[9];
    const float* be1 = (const float*)d_in[10];
    const float* W2  = (const float*)d_in[11];
    const float* b2  = (const float*)d_in[12];
    float* out = (float*)d_out;

    float* octr = (out_size >= BSZ*HID + BSZ*3) ? out + (size_t)BSZ*HID : nullptr;
    float* obat = (out_size >= BSZ*HID + BSZ*3 + BSZ) ? out + (size_t)BSZ*131 : nullptr;

    int sm0 = (C0*HID + C0*FSTR + 3*HID) * 4;
    int sm1 = (HID*HID + HID*FSTR + 5*HID) * 4;
    int sm2 = (HID*HID + HID*FSTR + 3*HID + 8*HID) * 4;
    cudaFuncSetAttribute(k_l0, cudaFuncAttributeMaxDynamicSharedMemorySize, sm0);
    cudaFuncSetAttribute(k_l1, cudaFuncAttributeMaxDynamicSharedMemorySize, sm1);
    cudaFuncSetAttribute(k_l2, cudaFuncAttributeMaxDynamicSharedMemorySize, sm2);

    k_zero<<<32, 256>>>();
    k_pos4<<<(BB*NPTS + 255)/256, 256>>>(pos);
    k_fps<<<BB, 1024>>>(pos, octr, obat);
    k_nbr<<<BSZ, 128>>>();
    k_l0<<<BSZ, 128, sm0>>>(x, W0, b0);
    k_prep<<<1, 128>>>(g0, be0, 0);
    k_l1<<<BSZ, 128, sm1>>>(W1, b1);
    k_prep<<<1, 128>>>(g1, be1, 1);
    k_l2<<<BSZ, 128, sm2>>>(W2, b2, out);
}